// round 2
// baseline (speedup 1.0000x reference)
#include <cuda_runtime.h>
#include <cstdint>

#define LEN 2048
#define CH 64
#define BM 64
#define BN 64
#define NWARP 4
#define NTHREAD 128
#define QK_STRIDE 72   // floats; 72 mod 32 = 8 -> conflict-free A/B frag loads
#define V_STRIDE 68    // floats; 68 mod 32 = 4 -> conflict-free V B-frag loads
#define P_STRIDE 68
#define SMEM_FLOATS (2*CH*QK_STRIDE + CH*V_STRIDE + BM*P_STRIDE)
#define SMEM_BYTES (SMEM_FLOATS * 4)

__device__ __forceinline__ float to_tf32(float x) {
    uint32_t u;
    asm("cvt.rna.tf32.f32 %0, %1;" : "=r"(u) : "f"(x));
    return __uint_as_float(u);
}

__device__ __forceinline__ void mma_m16n8k8(float& d0, float& d1, float& d2, float& d3,
                                            uint32_t a0, uint32_t a1, uint32_t a2, uint32_t a3,
                                            uint32_t b0, uint32_t b1) {
    asm volatile(
        "mma.sync.aligned.m16n8k8.row.col.f32.tf32.tf32.f32 "
        "{%0,%1,%2,%3}, {%4,%5,%6,%7}, {%8,%9}, {%0,%1,%2,%3};"
        : "+f"(d0), "+f"(d1), "+f"(d2), "+f"(d3)
        : "r"(a0), "r"(a1), "r"(a2), "r"(a3), "r"(b0), "r"(b1));
}

extern __shared__ float smem[];

__global__ void __launch_bounds__(NTHREAD)
attn_flash_tf32(const float* __restrict__ qkv, float* __restrict__ out) {
    float* Qs = smem;                    // [CH][QK_STRIDE], holds Q^T as [c][t]
    float* Ks = Qs + CH * QK_STRIDE;     // [c][s]
    float* Vs = Ks + CH * QK_STRIDE;     // [c][s], stride V_STRIDE
    float* Ps = Vs + CH * V_STRIDE;      // [t][s], stride P_STRIDE

    const int tid  = threadIdx.x;
    const int lane = tid & 31;
    const int warp = tid >> 5;
    const int q4 = lane & 3;    // thread-in-quad (col group)
    const int r4 = lane >> 2;   // row-in-group 0..7

    const int bh = blockIdx.y;          // 0..63
    const int b  = bh >> 4;
    const int h  = bh & 15;
    const int t0 = blockIdx.x * BM;

    const float* qp = qkv + ((size_t)b * 3072 + (size_t)h * 192) * LEN;
    const float* kp = qp + (size_t)64  * LEN;
    const float* vp = qp + (size_t)128 * LEN;

    // ---- load Q tile, fold 1/8 scale, round to tf32 ----
    for (int i = tid; i < CH * BM / 4; i += NTHREAD) {
        int c = i >> 4;            // 16 float4 per row of 64
        int t = (i & 15) << 2;
        float4 v = *(const float4*)(qp + (size_t)c * LEN + t0 + t);
        float* dst = Qs + c * QK_STRIDE + t;
        dst[0] = to_tf32(v.x * 0.125f);
        dst[1] = to_tf32(v.y * 0.125f);
        dst[2] = to_tf32(v.z * 0.125f);
        dst[3] = to_tf32(v.w * 0.125f);
    }

    float accO[8][4];
    #pragma unroll
    for (int j = 0; j < 8; j++)
        #pragma unroll
        for (int e = 0; e < 4; e++) accO[j][e] = 0.f;
    float m0 = -1e30f, m1 = -1e30f, l0 = 0.f, l1 = 0.f;

    const int rowA = warp * 16 + r4;   // local query row for a0/c0 (a1/c2 at +8)

    for (int s0 = 0; s0 < LEN; s0 += BN) {
        __syncthreads();  // prev-iter PV reads done (and Q load visible on iter 0)

        // ---- load K, V tiles as tf32 ----
        for (int i = tid; i < CH * BN / 4; i += NTHREAD) {
            int c = i >> 4;
            int s = (i & 15) << 2;
            float4 k4 = *(const float4*)(kp + (size_t)c * LEN + s0 + s);
            float* dk = Ks + c * QK_STRIDE + s;
            dk[0] = to_tf32(k4.x); dk[1] = to_tf32(k4.y);
            dk[2] = to_tf32(k4.z); dk[3] = to_tf32(k4.w);
            float4 v4 = *(const float4*)(vp + (size_t)c * LEN + s0 + s);
            float* dv = Vs + c * V_STRIDE + s;
            dv[0] = to_tf32(v4.x); dv[1] = to_tf32(v4.y);
            dv[2] = to_tf32(v4.z); dv[3] = to_tf32(v4.w);
        }
        __syncthreads();

        // ---- S = (Q/8) K^T : [BM x BN], this warp owns 16 rows ----
        float accS[8][4];
        #pragma unroll
        for (int j = 0; j < 8; j++)
            #pragma unroll
            for (int e = 0; e < 4; e++) accS[j][e] = 0.f;

        #pragma unroll
        for (int kk = 0; kk < 8; kk++) {
            const int c0 = kk * 8;
            uint32_t a0 = __float_as_uint(Qs[(c0 + q4)     * QK_STRIDE + rowA]);
            uint32_t a1 = __float_as_uint(Qs[(c0 + q4)     * QK_STRIDE + rowA + 8]);
            uint32_t a2 = __float_as_uint(Qs[(c0 + q4 + 4) * QK_STRIDE + rowA]);
            uint32_t a3 = __float_as_uint(Qs[(c0 + q4 + 4) * QK_STRIDE + rowA + 8]);
            #pragma unroll
            for (int j = 0; j < 8; j++) {
                uint32_t b0 = __float_as_uint(Ks[(c0 + q4)     * QK_STRIDE + j * 8 + r4]);
                uint32_t b1 = __float_as_uint(Ks[(c0 + q4 + 4) * QK_STRIDE + j * 8 + r4]);
                mma_m16n8k8(accS[j][0], accS[j][1], accS[j][2], accS[j][3],
                            a0, a1, a2, a3, b0, b1);
            }
        }

        // ---- online softmax ----
        float rm0 = -1e30f, rm1 = -1e30f;
        #pragma unroll
        for (int j = 0; j < 8; j++) {
            rm0 = fmaxf(rm0, fmaxf(accS[j][0], accS[j][1]));
            rm1 = fmaxf(rm1, fmaxf(accS[j][2], accS[j][3]));
        }
        rm0 = fmaxf(rm0, __shfl_xor_sync(0xffffffffu, rm0, 1));
        rm0 = fmaxf(rm0, __shfl_xor_sync(0xffffffffu, rm0, 2));
        rm1 = fmaxf(rm1, __shfl_xor_sync(0xffffffffu, rm1, 1));
        rm1 = fmaxf(rm1, __shfl_xor_sync(0xffffffffu, rm1, 2));

        float mn0 = fmaxf(m0, rm0), mn1 = fmaxf(m1, rm1);
        float cor0 = __expf(m0 - mn0), cor1 = __expf(m1 - mn1);
        m0 = mn0; m1 = mn1;
        l0 *= cor0; l1 *= cor1;
        #pragma unroll
        for (int j = 0; j < 8; j++) {
            accO[j][0] *= cor0; accO[j][1] *= cor0;
            accO[j][2] *= cor1; accO[j][3] *= cor1;
        }

        float rs0 = 0.f, rs1 = 0.f;
        #pragma unroll
        for (int j = 0; j < 8; j++) {
            accS[j][0] = __expf(accS[j][0] - m0);
            accS[j][1] = __expf(accS[j][1] - m0);
            accS[j][2] = __expf(accS[j][2] - m1);
            accS[j][3] = __expf(accS[j][3] - m1);
            rs0 += accS[j][0] + accS[j][1];
            rs1 += accS[j][2] + accS[j][3];
        }
        rs0 += __shfl_xor_sync(0xffffffffu, rs0, 1);
        rs0 += __shfl_xor_sync(0xffffffffu, rs0, 2);
        rs1 += __shfl_xor_sync(0xffffffffu, rs1, 1);
        rs1 += __shfl_xor_sync(0xffffffffu, rs1, 2);
        l0 += rs0; l1 += rs1;

        // ---- P -> smem (per-warp region), reload as A-frags ----
        #pragma unroll
        for (int j = 0; j < 8; j++) {
            int col = j * 8 + q4 * 2;
            Ps[rowA       * P_STRIDE + col    ] = to_tf32(accS[j][0]);
            Ps[rowA       * P_STRIDE + col + 1] = to_tf32(accS[j][1]);
            Ps[(rowA + 8) * P_STRIDE + col    ] = to_tf32(accS[j][2]);
            Ps[(rowA + 8) * P_STRIDE + col + 1] = to_tf32(accS[j][3]);
        }
        __syncwarp();

        // ---- O += P @ V^T ----
        #pragma unroll
        for (int kk = 0; kk < 8; kk++) {
            const int sb = kk * 8;
            uint32_t a0 = __float_as_uint(Ps[rowA       * P_STRIDE + sb + q4]);
            uint32_t a1 = __float_as_uint(Ps[(rowA + 8) * P_STRIDE + sb + q4]);
            uint32_t a2 = __float_as_uint(Ps[rowA       * P_STRIDE + sb + q4 + 4]);
            uint32_t a3 = __float_as_uint(Ps[(rowA + 8) * P_STRIDE + sb + q4 + 4]);
            #pragma unroll
            for (int j = 0; j < 8; j++) {
                uint32_t b0 = __float_as_uint(Vs[(j * 8 + r4) * V_STRIDE + sb + q4]);
                uint32_t b1 = __float_as_uint(Vs[(j * 8 + r4) * V_STRIDE + sb + q4 + 4]);
                mma_m16n8k8(accO[j][0], accO[j][1], accO[j][2], accO[j][3],
                            a0, a1, a2, a3, b0, b1);
            }
        }
    }

    // ---- epilogue: normalize, transpose through smem, coalesced store ----
    __syncthreads();   // everyone done reading Qs/Ks/Vs
    const float inv0 = 1.f / l0, inv1 = 1.f / l1;
    float* Os = Qs;    // reuse: [c][t], stride QK_STRIDE
    #pragma unroll
    for (int j = 0; j < 8; j++) {
        int col = j * 8 + q4 * 2;
        Os[col       * QK_STRIDE + rowA    ] = accO[j][0] * inv0;
        Os[(col + 1) * QK_STRIDE + rowA    ] = accO[j][1] * inv0;
        Os[col       * QK_STRIDE + rowA + 8] = accO[j][2] * inv1;
        Os[(col + 1) * QK_STRIDE + rowA + 8] = accO[j][3] * inv1;
    }
    __syncthreads();

    float* op = out + ((size_t)b * 1024 + (size_t)h * 64) * LEN + t0;
    for (int i = tid; i < CH * BM / 4; i += NTHREAD) {
        int c = i >> 4;
        int t = (i & 15) << 2;
        *(float4*)(op + (size_t)c * LEN + t) = *(const float4*)(Os + c * QK_STRIDE + t);
    }
}

extern "C" void kernel_launch(void* const* d_in, const int* in_sizes, int n_in,
                              void* d_out, int out_size) {
    const float* qkv = (const float*)d_in[0];
    float* out = (float*)d_out;
    cudaFuncSetAttribute(attn_flash_tf32,
                         cudaFuncAttributeMaxDynamicSharedMemorySize, SMEM_BYTES);
    dim3 grid(LEN / BM, 64);
    attn_flash_tf32<<<grid, NTHREAD, SMEM_BYTES>>>(qkv, out);
}